// round 8
// baseline (speedup 1.0000x reference)
#include <cuda_runtime.h>
#include <math_constants.h>
#include <stdint.h>

#define N_BINS  15
#define C_DIM   100
#define FULL    0xffffffffu
#define THREADS 256
#define BLOCKS  2368

// Persistent accumulators. Zero-initialized at module load; the LAST block of
// every launch resets them after consuming, so every launch (and every graph
// replay) starts from zero. Deterministic.
__device__ float    g_cnt[N_BINS];
__device__ double   g_conf[N_BINS];
__device__ float    g_accs[N_BINS];
__device__ unsigned g_ctr;

// Order-preserving float -> u32 map (u32 compare == float compare) and inverse.
__device__ __forceinline__ unsigned fmap(float f) {
    unsigned b = __float_as_uint(f);
    return ((int)b >= 0) ? (b | 0x80000000u) : ~b;
}
__device__ __forceinline__ float funmap(unsigned u) {
    unsigned b = (u & 0x80000000u) ? (u & 0x7fffffffu) : ~u;
    return __uint_as_float(b);
}

__global__ void __launch_bounds__(THREADS) ece_fused_kernel(
    const float* __restrict__ logits,
    const void*  __restrict__ labels_raw,
    float* __restrict__ out,
    int n, int vec_ok, float inv_n)
{
    __shared__ float s_cnt[N_BINS], s_conf[N_BINS], s_acc[N_BINS];
    __shared__ int   s_is64;
    __shared__ unsigned s_ticket;

    const int tid  = threadIdx.x;
    const int lane = tid & 31;

    if (tid < N_BINS) { s_cnt[tid] = 0.f; s_conf[tid] = 0.f; s_acc[tid] = 0.f; }

    // Label dtype detect (per block): odd int32 words all zero => int64.
    if (tid < 32) {
        int idx = 1 + 2 * tid;                 // words 1..63, far within buffer
        int v = (idx < n) ? ((const int*)labels_raw)[idx] : 0;
        unsigned any = __ballot_sync(FULL, v != 0);
        if (tid == 0) s_is64 = (any == 0) ? 1 : 0;
    }
    __syncthreads();

    const int is64 = s_is64;
    const int* __restrict__       lab32 = (const int*)labels_raw;
    const long long* __restrict__ lab64 = (const long long*)labels_raw;

    const int warp   = (int)((blockIdx.x * THREADS + tid) >> 5);
    const int nwarps = (BLOCKS * THREADS) >> 5;

    // Per-warp register histogram: lane b (b < 15) owns bin b.
    float r_cnt = 0.0f, r_conf = 0.0f, r_acc = 0.0f;

    if (vec_ok) {
        const float4* __restrict__ lg = reinterpret_cast<const float4*>(logits);

        // depth-2 software pipeline
        int row = warp;
        float4 v = make_float4(0.f, 0.f, 0.f, 0.f);
        int lab = 0;
        if (row < n) {
            if (lane < 25) v = lg[(size_t)row * 25 + lane];
            lab = is64 ? (int)lab64[row] : lab32[row];
        }

        while (row < n) {
            const int next = row + nwarps;
            float4 v2 = make_float4(0.f, 0.f, 0.f, 0.f);
            int lab2 = 0;
            if (next < n) {
                if (lane < 25) v2 = lg[(size_t)next * 25 + lane];
                lab2 = is64 ? (int)lab64[next] : lab32[next];
            }

            // lane-local max + first index
            float m  = -CUDART_INF_F;
            int   mi = 0x7fffffff;
            if (lane < 25) {
                int base = lane * 4;
                m = v.x; mi = base;
                if (v.y > m) { m = v.y; mi = base + 1; }
                if (v.z > m) { m = v.z; mi = base + 2; }
                if (v.w > m) { m = v.w; mi = base + 3; }
            }

            // warp argmax: redux max on mapped value, redux min on winning
            // indices (ties -> smallest index == jnp first-occurrence).
            unsigned mu   = fmap(m);
            unsigned maxu = __reduce_max_sync(FULL, mu);
            int cand = (mu == maxu) ? mi : 0x7fffffff;
            int ami  = __reduce_min_sync(FULL, cand);
            float mm = funmap(maxu);

            float conf = 1.0f / (1.0f + __expf(-mm));   // sigmoid monotone
            int bin = (int)ceilf(conf * 15.0f) - 1;     // searchsorted-left - 1
            bin = bin < 0 ? 0 : (bin > N_BINS - 1 ? N_BINS - 1 : bin);

            if (lane == bin) {
                r_cnt  += 1.0f;
                r_conf += conf;
                r_acc  += (ami == lab) ? 1.0f : 0.0f;
            }

            row = next; v = v2; lab = lab2;
        }
    } else {
        for (int row = warp; row < n; row += nwarps) {
            float m = -CUDART_INF_F; int mi = 0x7fffffff;
            #pragma unroll
            for (int j = 0; j < 4; j++) {
                int c = lane + j * 32;
                if (c < C_DIM) {
                    float x = logits[(size_t)row * C_DIM + c];
                    if (x > m) { m = x; mi = c; }
                }
            }
            int lab = is64 ? (int)lab64[row] : lab32[row];
            unsigned mu   = fmap(m);
            unsigned maxu = __reduce_max_sync(FULL, mu);
            int cand = (mu == maxu) ? mi : 0x7fffffff;
            int ami  = __reduce_min_sync(FULL, cand);
            float mm = funmap(maxu);
            float conf = 1.0f / (1.0f + __expf(-mm));
            int bin = (int)ceilf(conf * 15.0f) - 1;
            bin = bin < 0 ? 0 : (bin > N_BINS - 1 ? N_BINS - 1 : bin);
            if (lane == bin) {
                r_cnt += 1.0f; r_conf += conf;
                r_acc += (ami == lab) ? 1.0f : 0.0f;
            }
        }
    }

    // warp -> block (shared) -> global
    if (lane < N_BINS && r_cnt != 0.0f) {
        atomicAdd(&s_cnt[lane],  r_cnt);
        atomicAdd(&s_conf[lane], r_conf);
        atomicAdd(&s_acc[lane],  r_acc);
    }
    __syncthreads();
    if (tid < N_BINS) {
        float c = s_cnt[tid];
        if (c != 0.0f) {
            atomicAdd(&g_cnt[tid],  c);
            atomicAdd(&g_conf[tid], (double)s_conf[tid]);
            atomicAdd(&g_accs[tid], s_acc[tid]);
        }
    }

    // ticket: last block finalizes and resets state for the next launch
    __threadfence();
    if (tid == 0) s_ticket = atomicAdd(&g_ctr, 1u);
    __syncthreads();
    if (s_ticket == (unsigned)(gridDim.x - 1) && tid == 0) {
        __threadfence();
        float ece = 0.0f;
        #pragma unroll
        for (int b = 0; b < N_BINS; b++) {
            float cnt = g_cnt[b];
            if (cnt > 0.0f) {
                float avg_conf = (float)g_conf[b] / cnt;
                float avg_acc  = g_accs[b] / cnt;
                ece += (avg_conf - avg_acc) * (cnt * inv_n);
            }
            g_cnt[b] = 0.0f; g_conf[b] = 0.0; g_accs[b] = 0.0f;
        }
        out[0] = ece;
        g_ctr = 0u;
        __threadfence();
    }
}

extern "C" void kernel_launch(void* const* d_in, const int* in_sizes, int n_in,
                              void* d_out, int out_size) {
    // Resolve input order by element count (logits = C_DIM x labels count).
    long long s0 = in_sizes[0], s1 = in_sizes[1];
    int logits_idx = (s0 > s1) ? 0 : 1;
    int labels_idx = 1 - logits_idx;

    const float* logits     = (const float*)d_in[logits_idx];
    const void*  labels_raw = d_in[labels_idx];
    int n = (int)((s0 < s1) ? s0 : s1);
    float* out = (float*)d_out;

    int vec_ok = ((uintptr_t)logits & 15) == 0 ? 1 : 0;

    ece_fused_kernel<<<BLOCKS, THREADS>>>(logits, labels_raw, out, n, vec_ok,
                                          1.0f / (float)n);
}